// round 3
// baseline (speedup 1.0000x reference)
#include <cuda_runtime.h>
#include <cuda_bf16.h>
#include <math.h>
#include <stdint.h>

// Problem constants
#define BATCH 2
#define SEQ   2048
#define DMODEL 1024
#define NHEAD 16
#define DK    64
#define SCALE 0.35355339059327376f  // 64^-0.25
#define M_TOT (BATCH * SEQ)         // 4096

// Scratch (device globals: allocation-free rule)
__device__ float g_q[BATCH * NHEAD * SEQ * DK];   // [B,H,L,DK] pre-scaled
__device__ float g_k[BATCH * NHEAD * SEQ * DK];   // [B,H,L,DK] pre-scaled
__device__ float g_v[BATCH * NHEAD * SEQ * DK];   // [B,H,L,DK]
__device__ float g_attn[BATCH * SEQ * DMODEL];    // [B,L,D]

__device__ __forceinline__ uint32_t f2tf(float f) {
    uint32_t u;
    asm("cvt.rna.tf32.f32 %0, %1;" : "=r"(u) : "f"(f));
    return u;
}

__device__ __forceinline__ void mma_tf32(float* c, const uint32_t* a, const uint32_t* b) {
    asm volatile(
        "mma.sync.aligned.m16n8k8.row.col.f32.tf32.tf32.f32 "
        "{%0,%1,%2,%3}, {%4,%5,%6,%7}, {%8,%9}, {%0,%1,%2,%3};\n"
        : "+f"(c[0]), "+f"(c[1]), "+f"(c[2]), "+f"(c[3])
        : "r"(a[0]), "r"(a[1]), "r"(a[2]), "r"(a[3]), "r"(b[0]), "r"(b[1]));
}

// ---------------------------------------------------------------------------
// Projection GEMM (tf32 tensor cores): out = X @ W^T
// X: [M,1024] row-major, W: [1024,1024] row-major (rows = out features, K-major)
// Tile 128x128, BK=32, 256 threads = 8 warps as 4(m) x 2(n), warp tile 32x64.
// headMode==1: out[((b*H+h)*L+l)*DK+dk] = v*scale  (m=b*L+l, n=h*DK+dk)
// headMode==0: out[m*1024+n] = v
// ---------------------------------------------------------------------------
#define PPAD 36
__global__ __launch_bounds__(256) void proj_tf32(
    const float* __restrict__ X, const float* __restrict__ W,
    float* __restrict__ out, int headMode, float scale)
{
    __shared__ uint32_t As[128 * PPAD];
    __shared__ uint32_t Bs[128 * PPAD];

    const int tid = threadIdx.x;
    const int lane = tid & 31;
    const int warp = tid >> 5;
    const int wm = warp >> 1;         // 0..3
    const int wn = warp & 1;          // 0..1
    const int gr = lane >> 2;         // 0..7
    const int gc = lane & 3;          // 0..3
    const int m0 = blockIdx.y * 128;
    const int n0 = blockIdx.x * 128;

    float acc[2][8][4] = {};

    for (int k0 = 0; k0 < DMODEL; k0 += 32) {
#pragma unroll
        for (int p = 0; p < 4; p++) {
            int idx = tid + 256 * p;          // 0..1023
            int r = idx >> 3;                 // 0..127
            int c = (idx & 7) * 4;            // 0..28
            float4 a = *(const float4*)&X[(size_t)(m0 + r) * DMODEL + k0 + c];
            float4 b = *(const float4*)&W[(size_t)(n0 + r) * DMODEL + k0 + c];
            uint32_t* pa = &As[r * PPAD + c];
            pa[0] = f2tf(a.x); pa[1] = f2tf(a.y); pa[2] = f2tf(a.z); pa[3] = f2tf(a.w);
            uint32_t* pb = &Bs[r * PPAD + c];
            pb[0] = f2tf(b.x); pb[1] = f2tf(b.y); pb[2] = f2tf(b.z); pb[3] = f2tf(b.w);
        }
        __syncthreads();

#pragma unroll
        for (int kk = 0; kk < 32; kk += 8) {
            uint32_t afr[2][4], bfr[8][2];
#pragma unroll
            for (int mt = 0; mt < 2; mt++) {
                int rm = wm * 32 + mt * 16;
                afr[mt][0] = As[(rm + gr) * PPAD + kk + gc];
                afr[mt][1] = As[(rm + 8 + gr) * PPAD + kk + gc];
                afr[mt][2] = As[(rm + gr) * PPAD + kk + 4 + gc];
                afr[mt][3] = As[(rm + 8 + gr) * PPAD + kk + 4 + gc];
            }
#pragma unroll
            for (int nt = 0; nt < 8; nt++) {
                int cn = wn * 64 + nt * 8;
                bfr[nt][0] = Bs[(cn + gr) * PPAD + kk + gc];
                bfr[nt][1] = Bs[(cn + gr) * PPAD + kk + 4 + gc];
            }
#pragma unroll
            for (int mt = 0; mt < 2; mt++)
#pragma unroll
                for (int nt = 0; nt < 8; nt++)
                    mma_tf32(acc[mt][nt], afr[mt], bfr[nt]);
        }
        __syncthreads();
    }

    // epilogue
#pragma unroll
    for (int mt = 0; mt < 2; mt++) {
#pragma unroll
        for (int nt = 0; nt < 8; nt++) {
#pragma unroll
            for (int half = 0; half < 2; half++) {
                int m = m0 + wm * 32 + mt * 16 + gr + half * 8;
                int n = n0 + wn * 64 + nt * 8 + gc * 2;
                float v0 = acc[mt][nt][half * 2 + 0] * scale;
                float v1 = acc[mt][nt][half * 2 + 1] * scale;
                if (headMode) {
                    int b = m >> 11;
                    int l = m & 2047;
                    int h = n >> 6;
                    int dk = n & 63;
                    float* dst = &g_q[0]; // placeholder; use out
                    dst = out + ((((size_t)b * NHEAD + h) * SEQ + l) << 6) + dk;
                    dst[0] = v0; dst[1] = v1;
                } else {
                    float* dst = out + (size_t)m * DMODEL + n;
                    *(float2*)dst = make_float2(v0, v1);
                }
            }
        }
    }
}

// ---------------------------------------------------------------------------
// Flash attention (tf32 tensor cores) per (b,h).
// Block: 64 queries, 128 threads = 4 warps, each warp owns 16 query rows.
// Q fragments live in registers for the whole K loop.
// Smem: KP [64][68] (K tile, then reused for P), VT [64][68] (V transposed).
// ---------------------------------------------------------------------------
#define APAD 68
__global__ __launch_bounds__(128) void attn_tf32(
    const float* __restrict__ q, const float* __restrict__ k,
    const float* __restrict__ v, const float* __restrict__ pb,
    float* __restrict__ out)
{
    __shared__ uint32_t KP[64 * APAD];
    __shared__ uint32_t VT[64 * APAD];

    const int tid = threadIdx.x;
    const int lane = tid & 31;
    const int warp = tid >> 5;        // 0..3
    const int gr = lane >> 2;         // 0..7
    const int gc = lane & 3;          // 0..3
    const int bh = blockIdx.y;        // 0..31
    const int qb = blockIdx.x * 64;

    // Q fragments: [8 k-steps][4 regs], rows warp*16 .. +16
    uint32_t qa[8][4];
    {
        const float* qg = q + ((size_t)bh * SEQ + qb + warp * 16) * DK;
#pragma unroll
        for (int ks = 0; ks < 8; ks++) {
            qa[ks][0] = f2tf(qg[(size_t)gr * DK + ks * 8 + gc]);
            qa[ks][1] = f2tf(qg[(size_t)(gr + 8) * DK + ks * 8 + gc]);
            qa[ks][2] = f2tf(qg[(size_t)gr * DK + ks * 8 + 4 + gc]);
            qa[ks][3] = f2tf(qg[(size_t)(gr + 8) * DK + ks * 8 + 4 + gc]);
        }
    }

    float mrow[2] = {-INFINITY, -INFINITY};
    float lrow[2] = {0.f, 0.f};
    float oacc[8][4] = {};

    const float* kbase = k + (size_t)bh * SEQ * DK;
    const float* vbase = v + (size_t)bh * SEQ * DK;
    const float* pbbase = pb + ((size_t)bh * SEQ + qb + warp * 16) * SEQ;

    for (int kb = 0; kb < SEQ; kb += 64) {
        __syncthreads();   // previous tile fully consumed before overwrite
        {
            const float4* ksrc = (const float4*)(kbase + (size_t)kb * DK);
            const float4* vsrc = (const float4*)(vbase + (size_t)kb * DK);
#pragma unroll
            for (int p = 0; p < 8; p++) {
                int idx = tid + 128 * p;          // 0..1023
                int r = idx >> 4;                 // key 0..63
                int c = (idx & 15) * 4;           // dk 0..60
                float4 t = ksrc[idx];
                uint32_t* d = &KP[r * APAD + c];
                d[0] = f2tf(t.x); d[1] = f2tf(t.y); d[2] = f2tf(t.z); d[3] = f2tf(t.w);
                float4 u = vsrc[idx];
                VT[(c + 0) * APAD + r] = f2tf(u.x);
                VT[(c + 1) * APAD + r] = f2tf(u.y);
                VT[(c + 2) * APAD + r] = f2tf(u.z);
                VT[(c + 3) * APAD + r] = f2tf(u.w);
            }
        }
        __syncthreads();

        // S = Q K^T  (8 key n-tiles)
        float sacc[8][4] = {};
#pragma unroll
        for (int ks = 0; ks < 8; ks++) {
#pragma unroll
            for (int nt = 0; nt < 8; nt++) {
                uint32_t bfr[2];
                bfr[0] = KP[(nt * 8 + gr) * APAD + ks * 8 + gc];
                bfr[1] = KP[(nt * 8 + gr) * APAD + ks * 8 + 4 + gc];
                mma_tf32(sacc[nt], qa[ks], bfr);
            }
        }
        __syncthreads();   // all warps done reading K tile (KP becomes P buffer)

        // add posbias
#pragma unroll
        for (int nt = 0; nt < 8; nt++) {
            float2 p0 = *(const float2*)&pbbase[(size_t)gr * SEQ + kb + nt * 8 + gc * 2];
            float2 p1 = *(const float2*)&pbbase[(size_t)(gr + 8) * SEQ + kb + nt * 8 + gc * 2];
            sacc[nt][0] += p0.x; sacc[nt][1] += p0.y;
            sacc[nt][2] += p1.x; sacc[nt][3] += p1.y;
        }

        // online softmax (rows r = gr, gr+8; 4 lanes per row share via shfl 1,2)
#pragma unroll
        for (int r = 0; r < 2; r++) {
            float mx = -INFINITY;
#pragma unroll
            for (int nt = 0; nt < 8; nt++)
                mx = fmaxf(mx, fmaxf(sacc[nt][r * 2], sacc[nt][r * 2 + 1]));
            mx = fmaxf(mx, __shfl_xor_sync(0xffffffffu, mx, 1));
            mx = fmaxf(mx, __shfl_xor_sync(0xffffffffu, mx, 2));
            float mn = fmaxf(mrow[r], mx);
            float al = __expf(mrow[r] - mn);
            float rs = 0.f;
#pragma unroll
            for (int nt = 0; nt < 8; nt++) {
                sacc[nt][r * 2]     = __expf(sacc[nt][r * 2] - mn);
                sacc[nt][r * 2 + 1] = __expf(sacc[nt][r * 2 + 1] - mn);
                rs += sacc[nt][r * 2] + sacc[nt][r * 2 + 1];
            }
            rs += __shfl_xor_sync(0xffffffffu, rs, 1);
            rs += __shfl_xor_sync(0xffffffffu, rs, 2);
            lrow[r] = lrow[r] * al + rs;
            mrow[r] = mn;
#pragma unroll
            for (int dt = 0; dt < 8; dt++) {
                oacc[dt][r * 2]     *= al;
                oacc[dt][r * 2 + 1] *= al;
            }
        }

        // write P into KP (own warp rows only -> warp-local dependency)
        {
            int rm = warp * 16;
#pragma unroll
            for (int nt = 0; nt < 8; nt++) {
                uint2 w0 = make_uint2(f2tf(sacc[nt][0]), f2tf(sacc[nt][1]));
                uint2 w1 = make_uint2(f2tf(sacc[nt][2]), f2tf(sacc[nt][3]));
                *(uint2*)&KP[(rm + gr) * APAD + nt * 8 + gc * 2] = w0;
                *(uint2*)&KP[(rm + 8 + gr) * APAD + nt * 8 + gc * 2] = w1;
            }
        }
        __syncwarp();

        // O += P @ V  (contraction over 64 keys)
#pragma unroll
        for (int ks = 0; ks < 8; ks++) {
            uint32_t pa[4];
            int rm = warp * 16;
            pa[0] = KP[(rm + gr) * APAD + ks * 8 + gc];
            pa[1] = KP[(rm + 8 + gr) * APAD + ks * 8 + gc];
            pa[2] = KP[(rm + gr) * APAD + ks * 8 + 4 + gc];
            pa[3] = KP[(rm + 8 + gr) * APAD + ks * 8 + 4 + gc];
#pragma unroll
            for (int dt = 0; dt < 8; dt++) {
                uint32_t bfr[2];
                bfr[0] = VT[(dt * 8 + gr) * APAD + ks * 8 + gc];
                bfr[1] = VT[(dt * 8 + gr) * APAD + ks * 8 + 4 + gc];
                mma_tf32(oacc[dt], pa, bfr);
            }
        }
    }

    // write normalized output into [B, L, D]
    const int b = bh >> 4;
    const int h = bh & 15;
    float inv0 = 1.f / lrow[0];
    float inv1 = 1.f / lrow[1];
    float* dst = out + ((size_t)b * SEQ + qb + warp * 16) * DMODEL + h * DK;
#pragma unroll
    for (int dt = 0; dt < 8; dt++) {
        *(float2*)&dst[(size_t)gr * DMODEL + dt * 8 + gc * 2] =
            make_float2(oacc[dt][0] * inv0, oacc[dt][1] * inv0);
        *(float2*)&dst[(size_t)(gr + 8) * DMODEL + dt * 8 + gc * 2] =
            make_float2(oacc[dt][2] * inv1, oacc[dt][3] * inv1);
    }
}

// ---------------------------------------------------------------------------
// Launch
// ---------------------------------------------------------------------------
extern "C" void kernel_launch(void* const* d_in, const int* in_sizes, int n_in,
                              void* d_out, int out_size)
{
    const float* query = (const float*)d_in[0];
    const float* key   = (const float*)d_in[1];
    const float* value = (const float*)d_in[2];
    const float* pbias = (const float*)d_in[3];
    const float* Wq    = (const float*)d_in[4];
    const float* Wk    = (const float*)d_in[5];
    const float* Wv    = (const float*)d_in[6];
    const float* Wo    = (const float*)d_in[7];
    float* out = (float*)d_out;

    float *qp, *kp, *vp, *ap;
    cudaGetSymbolAddress((void**)&qp, g_q);
    cudaGetSymbolAddress((void**)&kp, g_k);
    cudaGetSymbolAddress((void**)&vp, g_v);
    cudaGetSymbolAddress((void**)&ap, g_attn);

    dim3 pgrid(DMODEL / 128, M_TOT / 128);   // (8, 32)
    proj_tf32<<<pgrid, 256>>>(query, Wq, qp, 1, SCALE);
    proj_tf32<<<pgrid, 256>>>(key,   Wk, kp, 1, SCALE);
    proj_tf32<<<pgrid, 256>>>(value, Wv, vp, 1, 1.0f);

    dim3 agrid(SEQ / 64, BATCH * NHEAD);     // (32, 32)
    attn_tf32<<<agrid, 128>>>(qp, kp, vp, pbias, ap);

    proj_tf32<<<pgrid, 256>>>(ap, Wo, out, 0, 1.0f);
}

// round 5
// speedup vs baseline: 1.1544x; 1.1544x over previous
#include <cuda_runtime.h>
#include <cuda_bf16.h>
#include <math.h>
#include <stdint.h>

#define BATCH 2
#define SEQ   2048
#define DMODEL 1024
#define NHEAD 16
#define DK    64
#define SCALE 0.35355339059327376f
#define M_TOT (BATCH * SEQ)

__device__ float g_q[BATCH * NHEAD * SEQ * DK];
__device__ float g_k[BATCH * NHEAD * SEQ * DK];
__device__ float g_v[BATCH * NHEAD * SEQ * DK];
__device__ float g_attn[BATCH * SEQ * DMODEL];

__device__ __forceinline__ uint32_t f2tf(float f) {
    uint32_t u; asm("cvt.rna.tf32.f32 %0, %1;" : "=r"(u) : "f"(f)); return u;
}
__device__ __forceinline__ uint32_t smem_u32(const void* p) {
    uint32_t a;
    asm("{ .reg .u64 t; cvta.to.shared.u64 t, %1; cvt.u32.u64 %0, t; }" : "=r"(a) : "l"(p));
    return a;
}
__device__ __forceinline__ void mma_hw(float* c, const uint32_t* a, const uint32_t* b) {
    asm volatile(
        "mma.sync.aligned.m16n8k8.row.col.f32.tf32.tf32.f32 "
        "{%0,%1,%2,%3}, {%4,%5,%6,%7}, {%8,%9}, {%0,%1,%2,%3};\n"
        : "+f"(c[0]), "+f"(c[1]), "+f"(c[2]), "+f"(c[3])
        : "r"(a[0]), "r"(a[1]), "r"(a[2]), "r"(a[3]), "r"(b[0]), "r"(b[1]));
}

#define CP16(dst, src) asm volatile("cp.async.cg.shared.global [%0], [%1], 16;" :: "r"(dst), "l"(src) : "memory")
#define CP_COMMIT()    asm volatile("cp.async.commit_group;" ::: "memory")
#define CP_WAIT1()     asm volatile("cp.async.wait_group 1;" ::: "memory")
#define CP_WAIT0()     asm volatile("cp.async.wait_group 0;" ::: "memory")

// ---------------- projection GEMM (unchanged, known-good) ------------------
#define PPAD 36
__global__ __launch_bounds__(256) void proj_tf32(
    const float* __restrict__ X, const float* __restrict__ W,
    float* __restrict__ out, int headMode, float scale)
{
    __shared__ uint32_t As[128 * PPAD];
    __shared__ uint32_t Bs[128 * PPAD];
    const int tid = threadIdx.x, lane = tid & 31, warp = tid >> 5;
    const int wm = warp >> 1, wn = warp & 1, gr = lane >> 2, gc = lane & 3;
    const int m0 = blockIdx.y * 128, n0 = blockIdx.x * 128;
    float acc[2][8][4] = {};

    for (int k0 = 0; k0 < DMODEL; k0 += 32) {
#pragma unroll
        for (int p = 0; p < 4; p++) {
            int idx = tid + 256 * p;
            int r = idx >> 3, c = (idx & 7) * 4;
            float4 a = *(const float4*)&X[(size_t)(m0 + r) * DMODEL + k0 + c];
            float4 b = *(const float4*)&W[(size_t)(n0 + r) * DMODEL + k0 + c];
            uint32_t* pa = &As[r * PPAD + c];
            pa[0] = f2tf(a.x); pa[1] = f2tf(a.y); pa[2] = f2tf(a.z); pa[3] = f2tf(a.w);
            uint32_t* pb = &Bs[r * PPAD + c];
            pb[0] = f2tf(b.x); pb[1] = f2tf(b.y); pb[2] = f2tf(b.z); pb[3] = f2tf(b.w);
        }
        __syncthreads();
#pragma unroll
        for (int kk = 0; kk < 32; kk += 8) {
            uint32_t afr[2][4], bfr[8][2];
#pragma unroll
            for (int mt = 0; mt < 2; mt++) {
                int rm = wm * 32 + mt * 16;
                afr[mt][0] = As[(rm + gr) * PPAD + kk + gc];
                afr[mt][1] = As[(rm + 8 + gr) * PPAD + kk + gc];
                afr[mt][2] = As[(rm + gr) * PPAD + kk + 4 + gc];
                afr[mt][3] = As[(rm + 8 + gr) * PPAD + kk + 4 + gc];
            }
#pragma unroll
            for (int nt = 0; nt < 8; nt++) {
                int cn = wn * 64 + nt * 8;
                bfr[nt][0] = Bs[(cn + gr) * PPAD + kk + gc];
                bfr[nt][1] = Bs[(cn + gr) * PPAD + kk + 4 + gc];
            }
#pragma unroll
            for (int mt = 0; mt < 2; mt++)
#pragma unroll
                for (int nt = 0; nt < 8; nt++)
                    mma_hw(acc[mt][nt], afr[mt], bfr[nt]);
        }
        __syncthreads();
    }
#pragma unroll
    for (int mt = 0; mt < 2; mt++)
#pragma unroll
        for (int nt = 0; nt < 8; nt++)
#pragma unroll
            for (int half = 0; half < 2; half++) {
                int m = m0 + wm * 32 + mt * 16 + gr + half * 8;
                int n = n0 + wn * 64 + nt * 8 + gc * 2;
                float v0 = acc[mt][nt][half * 2 + 0] * scale;
                float v1 = acc[mt][nt][half * 2 + 1] * scale;
                if (headMode) {
                    int b = m >> 11, l = m & 2047, h = n >> 6, dk = n & 63;
                    float* dst = out + ((((size_t)b * NHEAD + h) * SEQ + l) << 6) + dk;
                    dst[0] = v0; dst[1] = v1;
                } else {
                    *(float2*)(out + (size_t)m * DMODEL + n) = make_float2(v0, v1);
                }
            }
}

// ---------------- flash attention: cp.async double-buffered ----------------
// smem float offsets
#define KSTR 68
#define VSTR 72
#define K0F  0
#define K1F  (64 * KSTR)
#define V0F  (2 * 64 * KSTR)
#define V1F  (2 * 64 * KSTR + 64 * VSTR)
#define SMEM_ATT ((2 * 64 * KSTR + 2 * 64 * VSTR) * 4)   // 71680 bytes

__global__ __launch_bounds__(128, 3) void attn_cp(
    const float* __restrict__ q, const float* __restrict__ k,
    const float* __restrict__ v, const float* __restrict__ pb,
    float* __restrict__ out)
{
    extern __shared__ float smf[];
    const uint32_t sb = smem_u32(smf);
    const int tid = threadIdx.x, lane = tid & 31, warp = tid >> 5;
    const int gr = lane >> 2, gc = lane & 3;
    const int bh = blockIdx.y, qb = blockIdx.x * 64;

    // Q fragments (rna), rows warp*16..+16, held all loop
    uint32_t qa[8][4];
    {
        const float* qg = q + ((size_t)bh * SEQ + qb + warp * 16) * DK;
#pragma unroll
        for (int ks = 0; ks < 8; ks++) {
            qa[ks][0] = f2tf(qg[(size_t)gr * DK + ks * 8 + gc]);
            qa[ks][1] = f2tf(qg[(size_t)(gr + 8) * DK + ks * 8 + gc]);
            qa[ks][2] = f2tf(qg[(size_t)gr * DK + ks * 8 + 4 + gc]);
            qa[ks][3] = f2tf(qg[(size_t)(gr + 8) * DK + ks * 8 + 4 + gc]);
        }
    }

    float mrow[2] = {-INFINITY, -INFINITY};
    float lrow[2] = {0.f, 0.f};
    float oacc[8][4] = {};

    const float* kbase = k + (size_t)bh * SEQ * DK;
    const float* vbase = v + (size_t)bh * SEQ * DK;
    const float* pbbase = pb + ((size_t)bh * SEQ + qb + warp * 16) * SEQ;

    // prologue: stream tile 0 into buffer 0
    {
        const float4* kg = (const float4*)kbase;
        const float4* vg = (const float4*)vbase;
#pragma unroll
        for (int j = 0; j < 8; j++) {
            int c = tid + 128 * j;
            int row = c >> 4, qq = c & 15;
            CP16(sb + (K0F + row * KSTR + qq * 4) * 4, kg + c);
            CP16(sb + (V0F + row * VSTR + qq * 4) * 4, vg + c);
        }
        CP_COMMIT();
    }

    for (int kt = 0; kt < SEQ / 64; kt++) {
        const int cur = kt & 1;
        const int kb = kt * 64;

        // stream next tile into alternate buffer
        if (kt + 1 < SEQ / 64) {
            const float4* kg = (const float4*)(kbase + (size_t)(kb + 64) * DK);
            const float4* vg = (const float4*)(vbase + (size_t)(kb + 64) * DK);
            const int kf = cur ? K0F : K1F;
            const int vf = cur ? V0F : V1F;
#pragma unroll
            for (int j = 0; j < 8; j++) {
                int c = tid + 128 * j;
                int row = c >> 4, qq = c & 15;
                CP16(sb + (kf + row * KSTR + qq * 4) * 4, kg + c);
                CP16(sb + (vf + row * VSTR + qq * 4) * 4, vg + c);
            }
            CP_COMMIT();
        }

        // posbias prefetch (in flight under the MMAs)
        float2 pbv[16];
#pragma unroll
        for (int nt = 0; nt < 8; nt++) {
            pbv[nt]     = *(const float2*)&pbbase[(size_t)gr * SEQ + kb + nt * 8 + gc * 2];
            pbv[8 + nt] = *(const float2*)&pbbase[(size_t)(gr + 8) * SEQ + kb + nt * 8 + gc * 2];
        }

        if (kt + 1 < SEQ / 64) { CP_WAIT1(); } else { CP_WAIT0(); }
        __syncthreads();

        const float* Kc = smf + (cur ? K1F : K0F);
        const float* Vc = smf + (cur ? V1F : V0F);

        // S = Q K^T  (K raw fp32 bits -> tf32 truncation, softmax-shift-safe)
        float sacc[8][4] = {};
#pragma unroll
        for (int ks = 0; ks < 8; ks++) {
#pragma unroll
            for (int nt = 0; nt < 8; nt++) {
                uint32_t bfr[2];
                bfr[0] = __float_as_uint(Kc[(nt * 8 + gr) * KSTR + ks * 8 + gc]);
                bfr[1] = __float_as_uint(Kc[(nt * 8 + gr) * KSTR + ks * 8 + 4 + gc]);
                mma_hw(sacc[nt], qa[ks], bfr);
            }
        }
        __syncthreads();   // all warps done reading K tile (buffer becomes P)

        // posbias add
#pragma unroll
        for (int nt = 0; nt < 8; nt++) {
            sacc[nt][0] += pbv[nt].x;     sacc[nt][1] += pbv[nt].y;
            sacc[nt][2] += pbv[8 + nt].x; sacc[nt][3] += pbv[8 + nt].y;
        }

        // online softmax (rows gr, gr+8; 4 lanes/row via shfl 1,2)
#pragma unroll
        for (int r = 0; r < 2; r++) {
            float mx = -INFINITY;
#pragma unroll
            for (int nt = 0; nt < 8; nt++)
                mx = fmaxf(mx, fmaxf(sacc[nt][r * 2], sacc[nt][r * 2 + 1]));
            mx = fmaxf(mx, __shfl_xor_sync(0xffffffffu, mx, 1));
            mx = fmaxf(mx, __shfl_xor_sync(0xffffffffu, mx, 2));
            float mn = fmaxf(mrow[r], mx);
            float al = __expf(mrow[r] - mn);
            float rs = 0.f;
#pragma unroll
            for (int nt = 0; nt < 8; nt++) {
                sacc[nt][r * 2]     = __expf(sacc[nt][r * 2] - mn);
                sacc[nt][r * 2 + 1] = __expf(sacc[nt][r * 2 + 1] - mn);
                rs += sacc[nt][r * 2] + sacc[nt][r * 2 + 1];
            }
            rs += __shfl_xor_sync(0xffffffffu, rs, 1);
            rs += __shfl_xor_sync(0xffffffffu, rs, 2);
            lrow[r] = lrow[r] * al + rs;
            mrow[r] = mn;
#pragma unroll
            for (int dt = 0; dt < 8; dt++) {
                oacc[dt][r * 2]     *= al;
                oacc[dt][r * 2 + 1] *= al;
            }
        }

        // P (rna tf32) into current K buffer, own warp rows only
        {
            float* Pc = (float*)Kc;
            int rm = warp * 16;
#pragma unroll
            for (int nt = 0; nt < 8; nt++) {
                *(uint2*)&Pc[(rm + gr) * KSTR + nt * 8 + gc * 2] =
                    make_uint2(f2tf(sacc[nt][0]), f2tf(sacc[nt][1]));
                *(uint2*)&Pc[(rm + 8 + gr) * KSTR + nt * 8 + gc * 2] =
                    make_uint2(f2tf(sacc[nt][2]), f2tf(sacc[nt][3]));
            }
        }
        __syncwarp();

        // O += P @ V  (V untransposed: B(k,n) = V[key][dk]; rna at frag load)
        {
            const uint32_t* Pc = (const uint32_t*)Kc;
            int rm = warp * 16;
#pragma unroll
            for (int ks = 0; ks < 8; ks++) {
                uint32_t pa[4];
                pa[0] = Pc[(rm + gr) * KSTR + ks * 8 + gc];
                pa[1] = Pc[(rm + 8 + gr) * KSTR + ks * 8 + gc];
                pa[2] = Pc[(rm + gr) * KSTR + ks * 8 + 4 + gc];
                pa[3] = Pc[(rm + 8 + gr) * KSTR + ks * 8 + 4 + gc];
#pragma unroll
                for (int dt = 0; dt < 8; dt++) {
                    uint32_t bfr[2];
                    bfr[0] = f2tf(Vc[(ks * 8 + gc) * VSTR + dt * 8 + gr]);
                    bfr[1] = f2tf(Vc[(ks * 8 + 4 + gc) * VSTR + dt * 8 + gr]);
                    mma_hw(oacc[dt], pa, bfr);
                }
            }
        }
        __syncthreads();   // all warps done with this tile before buffers recycle
    }

    // normalized output -> [B, L, D]
    const int b = bh >> 4, h = bh & 15;
    float inv0 = 1.f / lrow[0];
    float inv1 = 1.f / lrow[1];
    float* dst = out + ((size_t)b * SEQ + qb + warp * 16) * DMODEL + h * DK;
#pragma unroll
    for (int dt = 0; dt < 8; dt++) {
        *(float2*)&dst[(size_t)gr * DMODEL + dt * 8 + gc * 2] =
            make_float2(oacc[dt][0] * inv0, oacc[dt][1] * inv0);
        *(float2*)&dst[(size_t)(gr + 8) * DMODEL + dt * 8 + gc * 2] =
            make_float2(oacc[dt][2] * inv1, oacc[dt][3] * inv1);
    }
}

// ---------------- launch ----------------------------------------------------
extern "C" void kernel_launch(void* const* d_in, const int* in_sizes, int n_in,
                              void* d_out, int out_size)
{
    const float* query = (const float*)d_in[0];
    const float* key   = (const float*)d_in[1];
    const float* value = (const float*)d_in[2];
    const float* pbias = (const float*)d_in[3];
    const float* Wq    = (const float*)d_in[4];
    const float* Wk    = (const float*)d_in[5];
    const float* Wv    = (const float*)d_in[6];
    const float* Wo    = (const float*)d_in[7];
    float* out = (float*)d_out;

    float *qp, *kp, *vp, *ap;
    cudaGetSymbolAddress((void**)&qp, g_q);
    cudaGetSymbolAddress((void**)&kp, g_k);
    cudaGetSymbolAddress((void**)&vp, g_v);
    cudaGetSymbolAddress((void**)&ap, g_attn);

    cudaFuncSetAttribute(attn_cp, cudaFuncAttributeMaxDynamicSharedMemorySize, SMEM_ATT);

    dim3 pgrid(DMODEL / 128, M_TOT / 128);
    proj_tf32<<<pgrid, 256>>>(query, Wq, qp, 1, SCALE);
    proj_tf32<<<pgrid, 256>>>(key,   Wk, kp, 1, SCALE);
    proj_tf32<<<pgrid, 256>>>(value, Wv, vp, 1, 1.0f);

    dim3 agrid(SEQ / 64, BATCH * NHEAD);     // (32, 32)
    attn_cp<<<agrid, 128, SMEM_ATT>>>(qp, kp, vp, pbias, ap);

    proj_tf32<<<pgrid, 256>>>(ap, Wo, out, 0, 1.0f);
}

// round 6
// speedup vs baseline: 1.2080x; 1.0464x over previous
#include <cuda_runtime.h>
#include <cuda_bf16.h>
#include <math.h>
#include <stdint.h>

#define BATCH 2
#define SEQ   2048
#define DMODEL 1024
#define NHEAD 16
#define DK    64
#define SCALE 0.35355339059327376f
#define M_TOT (BATCH * SEQ)

__device__ float g_q[BATCH * NHEAD * SEQ * DK];   // [bh][l][dk'] paired cols, tf32-rounded
__device__ float g_k[BATCH * NHEAD * SEQ * DK];   // [bh][l][dk'] paired cols, tf32-rounded
__device__ float g_v[BATCH * NHEAD * SEQ * DK];   // [bh][tile][kp][dk][2] key-paired, rounded
__device__ float g_attn[BATCH * SEQ * DMODEL];    // [B,L,D]

__device__ __forceinline__ uint32_t f2tf(float f) {
    uint32_t u; asm("cvt.rna.tf32.f32 %0, %1;" : "=r"(u) : "f"(f)); return u;
}
__device__ __forceinline__ uint32_t smem_u32(const void* p) {
    uint32_t a;
    asm("{ .reg .u64 t; cvta.to.shared.u64 t, %1; cvt.u32.u64 %0, t; }" : "=r"(a) : "l"(p));
    return a;
}
__device__ __forceinline__ void mma_hw(float* c, const uint32_t* a, const uint32_t* b) {
    asm volatile(
        "mma.sync.aligned.m16n8k8.row.col.f32.tf32.tf32.f32 "
        "{%0,%1,%2,%3}, {%4,%5,%6,%7}, {%8,%9}, {%0,%1,%2,%3};\n"
        : "+f"(c[0]), "+f"(c[1]), "+f"(c[2]), "+f"(c[3])
        : "r"(a[0]), "r"(a[1]), "r"(a[2]), "r"(a[3]), "r"(b[0]), "r"(b[1]));
}

#define CP16(dst, src) asm volatile("cp.async.cg.shared.global [%0], [%1], 16;" :: "r"(dst), "l"(src) : "memory")
#define CP_COMMIT()    asm volatile("cp.async.commit_group;" ::: "memory")
#define CP_WAIT1()     asm volatile("cp.async.wait_group 1;" ::: "memory")
#define CP_WAIT0()     asm volatile("cp.async.wait_group 0;" ::: "memory")

// paired-column permutation: (c, c+4) within each 8-group become adjacent
__device__ __forceinline__ int colperm(int dk) {
    return (dk & ~7) + ((dk & 3) << 1) + ((dk >> 2) & 1);
}

// ---------------- projection GEMM, pipelined loads -------------------------
// mode 0: plain [m][1024]; mode 1: Q/K [bh][l][colperm(dk)] rounded;
// mode 2: V [bh][l>>6][kp][dk][2] rounded (key-paired per 64-tile)
#define PPAD 36
__global__ __launch_bounds__(256) void proj_tf32(
    const float* __restrict__ X, const float* __restrict__ W,
    float* __restrict__ out, int mode, float scale)
{
    __shared__ uint32_t As[128 * PPAD];
    __shared__ uint32_t Bs[128 * PPAD];
    const int tid = threadIdx.x, lane = tid & 31, warp = tid >> 5;
    const int wm = warp >> 1, wn = warp & 1, gr = lane >> 2, gc = lane & 3;
    const int m0 = blockIdx.y * 128, n0 = blockIdx.x * 128;
    float acc[2][8][4] = {};

    float4 xa[4], wb[4];
#pragma unroll
    for (int p = 0; p < 4; p++) {
        int idx = tid + 256 * p;
        int r = idx >> 3, c = (idx & 7) * 4;
        xa[p] = *(const float4*)&X[(size_t)(m0 + r) * DMODEL + c];
        wb[p] = *(const float4*)&W[(size_t)(n0 + r) * DMODEL + c];
    }

    for (int k0 = 0; k0 < DMODEL; k0 += 32) {
#pragma unroll
        for (int p = 0; p < 4; p++) {
            int idx = tid + 256 * p;
            int r = idx >> 3, c = (idx & 7) * 4;
            uint32_t* pa = &As[r * PPAD + c];
            pa[0] = f2tf(xa[p].x); pa[1] = f2tf(xa[p].y); pa[2] = f2tf(xa[p].z); pa[3] = f2tf(xa[p].w);
            uint32_t* pb = &Bs[r * PPAD + c];
            pb[0] = f2tf(wb[p].x); pb[1] = f2tf(wb[p].y); pb[2] = f2tf(wb[p].z); pb[3] = f2tf(wb[p].w);
        }
        __syncthreads();
        if (k0 + 32 < DMODEL) {
#pragma unroll
            for (int p = 0; p < 4; p++) {
                int idx = tid + 256 * p;
                int r = idx >> 3, c = (idx & 7) * 4;
                xa[p] = *(const float4*)&X[(size_t)(m0 + r) * DMODEL + k0 + 32 + c];
                wb[p] = *(const float4*)&W[(size_t)(n0 + r) * DMODEL + k0 + 32 + c];
            }
        }
#pragma unroll
        for (int kk = 0; kk < 32; kk += 8) {
            uint32_t afr[2][4], bfr[8][2];
#pragma unroll
            for (int mt = 0; mt < 2; mt++) {
                int rm = wm * 32 + mt * 16;
                afr[mt][0] = As[(rm + gr) * PPAD + kk + gc];
                afr[mt][1] = As[(rm + 8 + gr) * PPAD + kk + gc];
                afr[mt][2] = As[(rm + gr) * PPAD + kk + 4 + gc];
                afr[mt][3] = As[(rm + 8 + gr) * PPAD + kk + 4 + gc];
            }
#pragma unroll
            for (int nt = 0; nt < 8; nt++) {
                int cn = wn * 64 + nt * 8;
                bfr[nt][0] = Bs[(cn + gr) * PPAD + kk + gc];
                bfr[nt][1] = Bs[(cn + gr) * PPAD + kk + 4 + gc];
            }
#pragma unroll
            for (int mt = 0; mt < 2; mt++)
#pragma unroll
                for (int nt = 0; nt < 8; nt++)
                    mma_hw(acc[mt][nt], afr[mt], bfr[nt]);
        }
        __syncthreads();
    }
#pragma unroll
    for (int mt = 0; mt < 2; mt++)
#pragma unroll
        for (int nt = 0; nt < 8; nt++)
#pragma unroll
            for (int half = 0; half < 2; half++) {
                int m = m0 + wm * 32 + mt * 16 + gr + half * 8;
                int n = n0 + wn * 64 + nt * 8 + gc * 2;
                float v0 = acc[mt][nt][half * 2 + 0] * scale;
                float v1 = acc[mt][nt][half * 2 + 1] * scale;
                if (mode == 0) {
                    *(float2*)(out + (size_t)m * DMODEL + n) = make_float2(v0, v1);
                } else {
                    int b = m >> 11, l = m & 2047, hh = n >> 6, dk = n & 63;
                    size_t base = ((size_t)b * NHEAD + hh) * SEQ * DK;
                    if (mode == 1) {
                        float* dst = out + base + (size_t)l * DK;
                        dst[colperm(dk)]     = __uint_as_float(f2tf(v0));
                        dst[colperm(dk + 1)] = __uint_as_float(f2tf(v1));
                    } else {
                        int tile = l >> 6, t = l & 63;
                        int kp = ((t >> 3) << 2) + (t & 3), hp = (t >> 2) & 1;
                        float* dst = out + base + (size_t)tile * 4096 + ((kp << 6) + dk) * 2 + hp;
                        dst[0] = __uint_as_float(f2tf(v0));
                        dst[2] = __uint_as_float(f2tf(v1));
                    }
                }
            }
}

// ---------------- flash attention ------------------------------------------
#define KSTR 72
#define PSTR 68
#define VSTR 136
#define K0F  0
#define K1F  (64 * KSTR)                       // 4608
#define V0F  (2 * 64 * KSTR)                   // 9216
#define V1F  (2 * 64 * KSTR + 32 * VSTR)       // 13568
#define SMEM_ATT ((2 * 64 * KSTR + 2 * 32 * VSTR) * 4)   // 71680 bytes

__global__ __launch_bounds__(128, 3) void attn_cp(
    const float* __restrict__ q, const float* __restrict__ k,
    const float* __restrict__ v, const float* __restrict__ pb,
    float* __restrict__ out)
{
    extern __shared__ float smf[];
    const uint32_t sb = smem_u32(smf);
    const int tid = threadIdx.x, lane = tid & 31, warp = tid >> 5;
    const int gr = lane >> 2, gc = lane & 3;
    const int bh = blockIdx.y, qb = blockIdx.x * 64;

    // Q fragments: paired-col gmem, pre-rounded -> raw uint2 loads
    uint32_t qa[8][4];
    {
        const float* qg = q + ((size_t)bh * SEQ + qb + warp * 16) * DK;
#pragma unroll
        for (int ks = 0; ks < 8; ks++) {
            uint2 t0 = *(const uint2*)&qg[(size_t)gr * DK + ks * 8 + gc * 2];
            uint2 t1 = *(const uint2*)&qg[(size_t)(gr + 8) * DK + ks * 8 + gc * 2];
            qa[ks][0] = t0.x; qa[ks][2] = t0.y;
            qa[ks][1] = t1.x; qa[ks][3] = t1.y;
        }
    }

    float mrow[2] = {-INFINITY, -INFINITY};
    float lrow[2] = {0.f, 0.f};
    float oacc[8][4] = {};

    const float* kbase = k + (size_t)bh * SEQ * DK;
    const float* vbase = v + (size_t)bh * SEQ * DK;
    const float* pbbase = pb + ((size_t)bh * SEQ + qb + warp * 16) * SEQ;

    // prologue: tile 0 -> buffer 0
    {
        const float4* kg = (const float4*)kbase;
        const float4* vg = (const float4*)vbase;   // tile 0 region, packed layout
#pragma unroll
        for (int j = 0; j < 8; j++) {
            int c = tid + 128 * j;
            CP16(sb + (K0F + (c >> 4) * KSTR + (c & 15) * 4) * 4, kg + c);
            CP16(sb + (V0F + (c >> 5) * VSTR + (c & 31) * 4) * 4, vg + c);
        }
        CP_COMMIT();
    }

    for (int kt = 0; kt < SEQ / 64; kt++) {
        const int cur = kt & 1;
        const int kb = kt * 64;

        if (kt + 1 < SEQ / 64) {
            const float4* kg = (const float4*)(kbase + (size_t)(kb + 64) * DK);
            const float4* vg = (const float4*)(vbase + (size_t)(kt + 1) * 4096);
            const int kf = cur ? K0F : K1F;
            const int vf = cur ? V0F : V1F;
#pragma unroll
            for (int j = 0; j < 8; j++) {
                int c = tid + 128 * j;
                CP16(sb + (kf + (c >> 4) * KSTR + (c & 15) * 4) * 4, kg + c);
                CP16(sb + (vf + (c >> 5) * VSTR + (c & 31) * 4) * 4, vg + c);
            }
            CP_COMMIT();
        }

        float2 pbv[16];
#pragma unroll
        for (int nt = 0; nt < 8; nt++) {
            pbv[nt]     = *(const float2*)&pbbase[(size_t)gr * SEQ + kb + nt * 8 + gc * 2];
            pbv[8 + nt] = *(const float2*)&pbbase[(size_t)(gr + 8) * SEQ + kb + nt * 8 + gc * 2];
        }

        if (kt + 1 < SEQ / 64) { CP_WAIT1(); } else { CP_WAIT0(); }
        __syncthreads();

        const float* Kc = smf + (cur ? K1F : K0F);
        const float* Vc = smf + (cur ? V1F : V0F);

        // S = Q K^T  (paired-col K, raw bits = exact rna)
        float sacc[8][4] = {};
#pragma unroll
        for (int ks = 0; ks < 8; ks++) {
#pragma unroll
            for (int nt = 0; nt < 8; nt++) {
                uint2 b = *(const uint2*)&Kc[(nt * 8 + gr) * KSTR + ks * 8 + gc * 2];
                uint32_t bfr[2] = { b.x, b.y };
                mma_hw(sacc[nt], qa[ks], bfr);
            }
        }
        __syncthreads();   // K buffer becomes P buffer

#pragma unroll
        for (int nt = 0; nt < 8; nt++) {
            sacc[nt][0] += pbv[nt].x;     sacc[nt][1] += pbv[nt].y;
            sacc[nt][2] += pbv[8 + nt].x; sacc[nt][3] += pbv[8 + nt].y;
        }

        // online softmax
#pragma unroll
        for (int r = 0; r < 2; r++) {
            float mx = -INFINITY;
#pragma unroll
            for (int nt = 0; nt < 8; nt++)
                mx = fmaxf(mx, fmaxf(sacc[nt][r * 2], sacc[nt][r * 2 + 1]));
            mx = fmaxf(mx, __shfl_xor_sync(0xffffffffu, mx, 1));
            mx = fmaxf(mx, __shfl_xor_sync(0xffffffffu, mx, 2));
            float mn = fmaxf(mrow[r], mx);
            float al = __expf(mrow[r] - mn);
            float rs = 0.f;
#pragma unroll
            for (int nt = 0; nt < 8; nt++) {
                sacc[nt][r * 2]     = __expf(sacc[nt][r * 2] - mn);
                sacc[nt][r * 2 + 1] = __expf(sacc[nt][r * 2 + 1] - mn);
                rs += sacc[nt][r * 2] + sacc[nt][r * 2 + 1];
            }
            rs += __shfl_xor_sync(0xffffffffu, rs, 1);
            rs += __shfl_xor_sync(0xffffffffu, rs, 2);
            lrow[r] = lrow[r] * al + rs;
            mrow[r] = mn;
#pragma unroll
            for (int dt = 0; dt < 8; dt++) {
                oacc[dt][r * 2]     *= al;
                oacc[dt][r * 2 + 1] *= al;
            }
        }

        // P (rna tf32) into K buffer, stride PSTR, own warp rows
        {
            float* Pc = (float*)Kc;
            int rm = warp * 16;
#pragma unroll
            for (int nt = 0; nt < 8; nt++) {
                *(uint2*)&Pc[(rm + gr) * PSTR + nt * 8 + gc * 2] =
                    make_uint2(f2tf(sacc[nt][0]), f2tf(sacc[nt][1]));
                *(uint2*)&Pc[(rm + 8 + gr) * PSTR + nt * 8 + gc * 2] =
                    make_uint2(f2tf(sacc[nt][2]), f2tf(sacc[nt][3]));
            }
        }
        __syncwarp();

        // O += P @ V  (key-paired V, raw uint2)
        {
            const float* Pc = Kc;
            int rm = warp * 16;
#pragma unroll
            for (int ks = 0; ks < 8; ks++) {
                uint32_t pa[4];
                pa[0] = __float_as_uint(Pc[(rm + gr) * PSTR + ks * 8 + gc]);
                pa[1] = __float_as_uint(Pc[(rm + 8 + gr) * PSTR + ks * 8 + gc]);
                pa[2] = __float_as_uint(Pc[(rm + gr) * PSTR + ks * 8 + 4 + gc]);
                pa[3] = __float_as_uint(Pc[(rm + 8 + gr) * PSTR + ks * 8 + 4 + gc]);
#pragma unroll
                for (int dt = 0; dt < 8; dt++) {
                    uint2 b = *(const uint2*)&Vc[(ks * 4 + gc) * VSTR + (dt * 8 + gr) * 2];
                    uint32_t bfr[2] = { b.x, b.y };
                    mma_hw(oacc[dt], pa, bfr);
                }
            }
        }
        __syncthreads();
    }

    const int b = bh >> 4, h = bh & 15;
    float inv0 = 1.f / lrow[0];
    float inv1 = 1.f / lrow[1];
    float* dst = out + ((size_t)b * SEQ + qb + warp * 16) * DMODEL + h * DK;
#pragma unroll
    for (int dt = 0; dt < 8; dt++) {
        *(float2*)&dst[(size_t)gr * DMODEL + dt * 8 + gc * 2] =
            make_float2(oacc[dt][0] * inv0, oacc[dt][1] * inv0);
        *(float2*)&dst[(size_t)(gr + 8) * DMODEL + dt * 8 + gc * 2] =
            make_float2(oacc[dt][2] * inv1, oacc[dt][3] * inv1);
    }
}

// ---------------- launch ----------------------------------------------------
extern "C" void kernel_launch(void* const* d_in, const int* in_sizes, int n_in,
                              void* d_out, int out_size)
{
    const float* query = (const float*)d_in[0];
    const float* key   = (const float*)d_in[1];
    const float* value = (const float*)d_in[2];
    const float* pbias = (const float*)d_in[3];
    const float* Wq    = (const float*)d_in[4];
    const float* Wk    = (const float*)d_in[5];
    const float* Wv    = (const float*)d_in[6];
    const float* Wo    = (const float*)d_in[7];
    float* out = (float*)d_out;

    float *qp, *kp, *vp, *ap;
    cudaGetSymbolAddress((void**)&qp, g_q);
    cudaGetSymbolAddress((void**)&kp, g_k);
    cudaGetSymbolAddress((void**)&vp, g_v);
    cudaGetSymbolAddress((void**)&ap, g_attn);

    cudaFuncSetAttribute(attn_cp, cudaFuncAttributeMaxDynamicSharedMemorySize, SMEM_ATT);

    dim3 pgrid(DMODEL / 128, M_TOT / 128);
    proj_tf32<<<pgrid, 256>>>(query, Wq, qp, 1, SCALE);
    proj_tf32<<<pgrid, 256>>>(key,   Wk, kp, 1, SCALE);
    proj_tf32<<<pgrid, 256>>>(value, Wv, vp, 2, 1.0f);

    dim3 agrid(SEQ / 64, BATCH * NHEAD);     // (32, 32)
    attn_cp<<<agrid, 128, SMEM_ATT>>>(qp, kp, vp, pbias, ap);

    proj_tf32<<<pgrid, 256>>>(ap, Wo, out, 0, 1.0f);
}